// round 2
// baseline (speedup 1.0000x reference)
#include <cuda_runtime.h>
#include <math.h>

#define Bc 256
#define Vc 4096
#define Kc 64
#define MINIf 1e-6f

#define VK (Vc*Kc)             /* 262144 */
#define BK (Bc*Kc)             /* 16384  */
#define OUT_TN 0
#define OUT_TM VK
#define OUT_QZ (VK+BK)
#define OUT_NN (VK+BK+1)
#define OUT_NM (VK+BK+1+VK)

// device scratch (static globals: allowed)
__device__ float g_theta[BK];
__device__ float g_thetaL[BK];
__device__ float g_phi[VK];
__device__ float g_phiL[VK];
__device__ float g_W[Bc*Vc];
__device__ float g_Nacc[VK];
__device__ float g_Macc[BK];
__device__ float g_denom[Kc];
__device__ float g_rho;
__device__ float g_ratio;
__device__ int   g_idxstride;

// ---------------------------------------------------------------------------
// K1: per-topic denominator, scalars, index-dtype probe, zero entropy slot.
__global__ void k1_denom(const float* __restrict__ beta,
                         const float* __restrict__ expn,
                         const int* __restrict__ iterp,
                         const int* __restrict__ cmp,
                         const int* __restrict__ bcp,
                         const unsigned int* __restrict__ idxw,
                         float* __restrict__ out) {
    if (blockIdx.x < Kc) {
        int k = blockIdx.x;
        float s = 0.f;
        for (int v = threadIdx.x; v < Vc; v += 256) {
            int i = v * Kc + k;
            s += beta[i] + expn[i];
        }
        __shared__ float red[256];
        red[threadIdx.x] = s;
        __syncthreads();
        for (int off = 128; off; off >>= 1) {
            if (threadIdx.x < off) red[threadIdx.x] += red[threadIdx.x + off];
            __syncthreads();
        }
        if (threadIdx.x == 0) g_denom[k] = red[0];
    } else if (threadIdx.x == 0) {
        g_rho   = 1.f / powf((float)(iterp[0] + 5), 0.9f);
        g_ratio = (float)cmp[0] / (float)bcp[0];
        // batch_indices dtype probe: values < 2^31 and >= 0. If the buffer is
        // int64, every odd 32-bit word (high half) is zero. If int32, the odd
        // words are 128 random values in [0,10000) -> all-zero is impossible.
        bool allz = true;
        for (int i = 1; i < Bc; i += 2)
            if (idxw[i] != 0u) { allz = false; break; }
        g_idxstride = allz ? 2 : 1;
        out[OUT_QZ] = 0.f;
    }
}

// ---------------------------------------------------------------------------
// K2: phi, phi*log(phi), theta (gathered), theta*log(theta); zero accumulators.
__global__ void k2_prep(const float* __restrict__ beta,
                        const float* __restrict__ expn,
                        const float* __restrict__ alpha,
                        const float* __restrict__ pi,
                        const float* __restrict__ expm,
                        const unsigned int* __restrict__ idxw) {
    int i = blockIdx.x * 256 + threadIdx.x;
    if (i < VK) {
        int k = i & (Kc - 1);
        float p = __fdividef(beta[i] + expn[i], g_denom[k]);
        g_phi[i]  = p;
        g_phiL[i] = p * __logf(p);
    } else if (i < VK + BK) {
        int j = i - VK;
        int b = j >> 6, k = j & 63;
        int d = (int)idxw[b * g_idxstride];
        float th = alpha[k] * pi[d * Kc + k] + expm[d * Kc + k];
        g_theta[j]  = th;
        g_thetaL[j] = th * __logf(th);
    } else if (i < 2 * VK + BK) {
        g_Nacc[i - VK - BK] = 0.f;
    } else if (i < 2 * VK + 2 * BK) {
        g_Macc[i - 2 * VK - BK] = 0.f;
    }
}

// ---------------------------------------------------------------------------
// K3: per (b,v): S = theta.phi, A = thetaL.phi + theta.phiL.
// w = cnt/(S+MINI) -> g_W ; entropy += (A - S*log(S+MINI))/(S+MINI) if cnt>0.
// Block tile 64b x 32v, 256 threads, register tile 2b x 4v (v strided by 8).
// smem rows padded to 68 floats: 16B aligned rows, 4-bank shift per row ->
// conflict-free broadcast LDS.128.
__global__ void __launch_bounds__(256)
k3_main(const int* __restrict__ bow, float* __restrict__ out) {
    extern __shared__ float sm3[];
    float (*th)[68]  = (float(*)[68])(sm3);
    float (*thL)[68] = (float(*)[68])(sm3 + 64 * 68);
    float (*ph)[68]  = (float(*)[68])(sm3 + 128 * 68);
    float (*phL)[68] = (float(*)[68])(sm3 + 160 * 68);

    int t = threadIdx.x;
    int v0 = blockIdx.x * 32;
    int b0 = blockIdx.y * 64;

    for (int i = t; i < 64 * 16; i += 256) {
        int r = i >> 4, cq = i & 15;
        *(float4*)&th [r][cq * 4] = ((const float4*)g_theta )[(b0 + r) * 16 + cq];
        *(float4*)&thL[r][cq * 4] = ((const float4*)g_thetaL)[(b0 + r) * 16 + cq];
    }
    for (int i = t; i < 32 * 16; i += 256) {
        int r = i >> 4, cq = i & 15;
        *(float4*)&ph [r][cq * 4] = ((const float4*)g_phi )[(v0 + r) * 16 + cq];
        *(float4*)&phL[r][cq * 4] = ((const float4*)g_phiL)[(v0 + r) * 16 + cq];
    }
    __syncthreads();

    int vg = t & 7;        // v_local = vg + 8*vi
    int bg = t >> 3;       // b_local = bg, bg+32

    float S[2][4] = {{0.f,0.f,0.f,0.f},{0.f,0.f,0.f,0.f}};
    float A[2][4] = {{0.f,0.f,0.f,0.f},{0.f,0.f,0.f,0.f}};

    #pragma unroll 4
    for (int kq = 0; kq < 16; ++kq) {
        float4 t0 = *(const float4*)&th [bg     ][kq * 4];
        float4 t1 = *(const float4*)&th [bg + 32][kq * 4];
        float4 l0 = *(const float4*)&thL[bg     ][kq * 4];
        float4 l1 = *(const float4*)&thL[bg + 32][kq * 4];
        #pragma unroll
        for (int vi = 0; vi < 4; ++vi) {
            float4 p = *(const float4*)&ph [vg + 8 * vi][kq * 4];
            float4 q = *(const float4*)&phL[vg + 8 * vi][kq * 4];
            S[0][vi] += t0.x*p.x + t0.y*p.y + t0.z*p.z + t0.w*p.w;
            S[1][vi] += t1.x*p.x + t1.y*p.y + t1.z*p.z + t1.w*p.w;
            A[0][vi] += l0.x*p.x + l0.y*p.y + l0.z*p.z + l0.w*p.w
                      + t0.x*q.x + t0.y*q.y + t0.z*q.z + t0.w*q.w;
            A[1][vi] += l1.x*p.x + l1.y*p.y + l1.z*p.z + l1.w*p.w
                      + t1.x*q.x + t1.y*q.y + t1.z*q.z + t1.w*q.w;
        }
    }

    float ent = 0.f;
    #pragma unroll
    for (int bi = 0; bi < 2; ++bi) {
        int b = b0 + bg + 32 * bi;
        #pragma unroll
        for (int vi = 0; vi < 4; ++vi) {
            int v = v0 + vg + 8 * vi;
            int cnt = bow[b * Vc + v];
            float sp = S[bi][vi] + MINIf;
            float r  = __fdividef(1.f, sp);
            g_W[b * Vc + v] = (float)cnt * r;
            if (cnt > 0)
                ent += (A[bi][vi] - S[bi][vi] * __logf(sp)) * r;
        }
    }

    // block entropy reduction
    #pragma unroll
    for (int o = 16; o; o >>= 1)
        ent += __shfl_xor_sync(0xFFFFFFFFu, ent, o);
    __shared__ float ered[8];
    if ((t & 31) == 0) ered[t >> 5] = ent;
    __syncthreads();
    if (t == 0) {
        float s = 0.f;
        #pragma unroll
        for (int w = 0; w < 8; ++w) s += ered[w];
        atomicAdd(&out[OUT_QZ], s);
    }
}

// ---------------------------------------------------------------------------
// K4: Macc[b,k] += sum_v W[b,v] * phi[v,k].  Grid (32 v-chunks, 4 b-blocks).
__global__ void __launch_bounds__(256) k4_WPhi() {
    int t = threadIdx.x;
    int kq = t & 15, br = t >> 4;
    int vbase0 = blockIdx.x * 128;
    int b0 = blockIdx.y * 64;
    __shared__ float Wt[64][33];
    __shared__ float pht[32][68];
    float4 acc[4] = {};
    for (int vt = 0; vt < 4; ++vt) {
        int vbase = vbase0 + vt * 32;
        __syncthreads();
        for (int i = t; i < 2048; i += 256) {
            int r = i >> 5, c = i & 31;
            Wt[r][c] = g_W[(b0 + r) * Vc + vbase + c];
        }
        for (int i = t; i < 512; i += 256) {
            int r = i >> 4, cq = i & 15;
            *(float4*)&pht[r][cq * 4] = ((const float4*)g_phi)[(vbase + r) * 16 + cq];
        }
        __syncthreads();
        #pragma unroll 8
        for (int c = 0; c < 32; ++c) {
            float4 p = *(const float4*)&pht[c][kq * 4];
            #pragma unroll
            for (int j = 0; j < 4; ++j) {
                float w = Wt[br + 16 * j][c];
                acc[j].x += w * p.x; acc[j].y += w * p.y;
                acc[j].z += w * p.z; acc[j].w += w * p.w;
            }
        }
    }
    #pragma unroll
    for (int j = 0; j < 4; ++j) {
        float* dst = &g_Macc[(b0 + br + 16 * j) * Kc + kq * 4];
        atomicAdd(dst + 0, acc[j].x); atomicAdd(dst + 1, acc[j].y);
        atomicAdd(dst + 2, acc[j].z); atomicAdd(dst + 3, acc[j].w);
    }
}

// ---------------------------------------------------------------------------
// K5: Nacc[v,k] += sum_b W[b,v] * theta[b,k].  Grid (64 v-blocks, 4 b-chunks).
__global__ void __launch_bounds__(256) k5_WtTheta() {
    int t = threadIdx.x;
    int kq = t & 15, vr = t >> 4;
    int v0 = blockIdx.x * 64;
    int bbase0 = blockIdx.y * 64;
    __shared__ float Wt[32][65];
    __shared__ float tht[32][68];
    float4 acc[4] = {};
    for (int bt = 0; bt < 2; ++bt) {
        int bbase = bbase0 + bt * 32;
        __syncthreads();
        for (int i = t; i < 2048; i += 256) {
            int c = i >> 6, v = i & 63;
            Wt[c][v] = g_W[(bbase + c) * Vc + v0 + v];
        }
        for (int i = t; i < 512; i += 256) {
            int r = i >> 4, cq = i & 15;
            *(float4*)&tht[r][cq * 4] = ((const float4*)g_theta)[(bbase + r) * 16 + cq];
        }
        __syncthreads();
        #pragma unroll 8
        for (int c = 0; c < 32; ++c) {
            float4 th4 = *(const float4*)&tht[c][kq * 4];
            #pragma unroll
            for (int j = 0; j < 4; ++j) {
                float w = Wt[c][vr + 16 * j];
                acc[j].x += w * th4.x; acc[j].y += w * th4.y;
                acc[j].z += w * th4.z; acc[j].w += w * th4.w;
            }
        }
    }
    #pragma unroll
    for (int j = 0; j < 4; ++j) {
        float* dst = &g_Nacc[(v0 + vr + 16 * j) * Kc + kq * 4];
        atomicAdd(dst + 0, acc[j].x); atomicAdd(dst + 1, acc[j].y);
        atomicAdd(dst + 2, acc[j].z); atomicAdd(dst + 3, acc[j].w);
    }
}

// ---------------------------------------------------------------------------
// K6: epilogue — apply phi/theta factors, SVI updates, write outputs.
__global__ void k6_epi(const float* __restrict__ expn,
                       const float* __restrict__ expm,
                       const unsigned int* __restrict__ idxw,
                       float* __restrict__ out) {
    int i = blockIdx.x * 256 + threadIdx.x;
    float rho = g_rho, omr = 1.f - rho;
    if (i < VK) {
        float tn = g_phi[i] * g_Nacc[i];
        out[OUT_TN + i] = tn;
        out[OUT_NN + i] = omr * expn[i] + rho * g_ratio * tn;
    } else if (i < VK + BK) {
        int j = i - VK;
        float tm = g_theta[j] * g_Macc[j];
        out[OUT_TM + j] = tm;
        int b = j >> 6, k = j & 63;
        int d = (int)idxw[b * g_idxstride];
        out[OUT_NM + j] = omr * expm[d * Kc + k] + rho * tm;
    }
}

// ---------------------------------------------------------------------------
extern "C" void kernel_launch(void* const* d_in, const int* in_sizes, int n_in,
                              void* d_out, int out_size) {
    const int*          bow   = (const int*)d_in[0];
    const unsigned int* idxw  = (const unsigned int*)d_in[1];
    const float*        alpha = (const float*)d_in[2];
    const float*        pi    = (const float*)d_in[3];
    const float*        expm  = (const float*)d_in[4];
    const float*        beta  = (const float*)d_in[5];
    const float*        expn  = (const float*)d_in[6];
    const int*          iterp = (const int*)d_in[7];
    const int*          cmp   = (const int*)d_in[8];
    const int*          bcp   = (const int*)d_in[9];
    float* out = (float*)d_out;

    static int smem_set = 0;
    const int k3_smem = 192 * 68 * 4;  // 52224 bytes
    if (!smem_set) {
        cudaFuncSetAttribute(k3_main, cudaFuncAttributeMaxDynamicSharedMemorySize, k3_smem);
        smem_set = 1;
    }

    k1_denom<<<Kc + 1, 256>>>(beta, expn, iterp, cmp, bcp, idxw, out);
    k2_prep<<<(2 * (VK + BK)) / 256, 256>>>(beta, expn, alpha, pi, expm, idxw);
    dim3 g3(Vc / 32, Bc / 64);
    k3_main<<<g3, 256, k3_smem>>>(bow, out);
    dim3 g4(Vc / 128, Bc / 64);
    k4_WPhi<<<g4, 256>>>();
    dim3 g5(Vc / 64, Bc / 64);
    k5_WtTheta<<<g5, 256>>>();
    k6_epi<<<(VK + BK) / 256, 256>>>(expn, expm, idxw, out);
}

// round 3
// speedup vs baseline: 1.4356x; 1.4356x over previous
#include <cuda_runtime.h>
#include <math.h>

#define Bc 256
#define Vc 4096
#define Kc 64
#define MINIf 1e-6f

#define VK (Vc*Kc)             /* 262144 */
#define BK (Bc*Kc)             /* 16384  */
#define OUT_TN 0
#define OUT_TM VK
#define OUT_QZ (VK+BK)
#define OUT_NN (VK+BK+1)
#define OUT_NM (VK+BK+1+VK)

// device scratch
__device__ float g_theta[BK];
__device__ float g_thetaL[BK];
__device__ float g_phi[VK];
__device__ float g_phiL[VK];
__device__ float g_Nacc[VK];
__device__ float g_Mpart[256 * 4096];   // [vblk*4+bblk][64b x 64k] partials, 4MB
__device__ float g_denom[Kc];
__device__ float g_rho;
__device__ float g_ratio;
__device__ int   g_idxstride;

// ---- packed f32x2 helpers (Blackwell FFMA2) --------------------------------
__device__ __forceinline__ void pfma(unsigned long long& acc,
                                     unsigned long long a, unsigned long long b) {
    asm("fma.rn.f32x2 %0, %1, %2, %0;" : "+l"(acc) : "l"(a), "l"(b));
}
__device__ __forceinline__ float psum(unsigned long long v) {
    return __uint_as_float((unsigned)v) + __uint_as_float((unsigned)(v >> 32));
}
__device__ __forceinline__ unsigned long long fpack2(float lo, float hi) {
    unsigned long long r;
    asm("mov.b64 %0, {%1, %2};" : "=l"(r) : "f"(lo), "f"(hi));
    return r;
}
__device__ __forceinline__ void punpack(unsigned long long v, float& lo, float& hi) {
    lo = __uint_as_float((unsigned)v);
    hi = __uint_as_float((unsigned)(v >> 32));
}

// ---------------------------------------------------------------------------
// K1: per-topic denominator, scalars, index-dtype probe, zero entropy slot.
__global__ void k1_denom(const float* __restrict__ beta,
                         const float* __restrict__ expn,
                         const int* __restrict__ iterp,
                         const int* __restrict__ cmp,
                         const int* __restrict__ bcp,
                         const unsigned int* __restrict__ idxw,
                         float* __restrict__ out) {
    if (blockIdx.x < Kc) {
        int k = blockIdx.x;
        float s = 0.f;
        for (int v = threadIdx.x; v < Vc; v += 256) {
            int i = v * Kc + k;
            s += beta[i] + expn[i];
        }
        __shared__ float red[256];
        red[threadIdx.x] = s;
        __syncthreads();
        for (int off = 128; off; off >>= 1) {
            if (threadIdx.x < off) red[threadIdx.x] += red[threadIdx.x + off];
            __syncthreads();
        }
        if (threadIdx.x == 0) g_denom[k] = red[0];
    } else if (threadIdx.x == 0) {
        g_rho   = 1.f / powf((float)(iterp[0] + 5), 0.9f);
        g_ratio = (float)cmp[0] / (float)bcp[0];
        // int64-vs-int32 probe: if int64, odd 32-bit words (high halves) are 0.
        bool allz = true;
        for (int i = 1; i < Bc; i += 2)
            if (idxw[i] != 0u) { allz = false; break; }
        g_idxstride = allz ? 2 : 1;
        out[OUT_QZ] = 0.f;
    }
}

// ---------------------------------------------------------------------------
// K2: phi, phi*log(phi), theta (gathered), theta*log(theta); zero Nacc.
__global__ void k2_prep(const float* __restrict__ beta,
                        const float* __restrict__ expn,
                        const float* __restrict__ alpha,
                        const float* __restrict__ pi,
                        const float* __restrict__ expm,
                        const unsigned int* __restrict__ idxw) {
    int i = blockIdx.x * 256 + threadIdx.x;
    if (i < VK) {
        int k = i & (Kc - 1);
        float p = __fdividef(beta[i] + expn[i], g_denom[k]);
        g_phi[i]  = p;
        g_phiL[i] = p * __logf(p);
    } else if (i < VK + BK) {
        int j = i - VK;
        int b = j >> 6, k = j & 63;
        int d = (int)idxw[b * g_idxstride];
        float th = alpha[k] * pi[d * Kc + k] + expm[d * Kc + k];
        g_theta[j]  = th;
        g_thetaL[j] = th * __logf(th);
    } else if (i < 2 * VK + BK) {
        g_Nacc[i - VK - BK] = 0.f;
    }
}

// ---------------------------------------------------------------------------
// K3 fused: per block 64b x 64v tile.
// Phase 1: S = theta.phi, A = thetaL.phi + theta.phiL per (b,v); w = cnt/(S+MINI)
//          entropy += (A - S*log(S+MINI))/(S+MINI) for cnt>0.
// Phase 2: Mpart[blk] = W(64x64) @ phi(64x64)   (partial over this v-tile)
//          Nacc     += W^T(64x64) @ theta(64x64) (atomics, depth 4)
// smem rows padded to 68 floats (16B-aligned rows, conflict-free-optimal LDS.128).
__global__ void __launch_bounds__(256, 2)
k3_fused(const int* __restrict__ bow, float* __restrict__ out) {
    extern __shared__ float sm3[];
    float (*th)[68]  = (float(*)[68])(sm3);
    float (*thL)[68] = (float(*)[68])(sm3 + 64 * 68);   // becomes Wt in phase 2
    float (*ph)[68]  = (float(*)[68])(sm3 + 128 * 68);
    float (*phL)[68] = (float(*)[68])(sm3 + 192 * 68);
    float (*Wt)[68]  = thL;

    int t = threadIdx.x;
    int v0 = blockIdx.x * 64;
    int b0 = blockIdx.y * 64;

    for (int i = t; i < 64 * 16; i += 256) {
        int r = i >> 4, cq = i & 15;
        *(float4*)&th [r][cq * 4] = ((const float4*)g_theta )[(b0 + r) * 16 + cq];
        *(float4*)&thL[r][cq * 4] = ((const float4*)g_thetaL)[(b0 + r) * 16 + cq];
        *(float4*)&ph [r][cq * 4] = ((const float4*)g_phi   )[(v0 + r) * 16 + cq];
        *(float4*)&phL[r][cq * 4] = ((const float4*)g_phiL  )[(v0 + r) * 16 + cq];
    }
    __syncthreads();

    int tv = t & 15;       // v_local = tv + 16*vi
    int tb = t >> 4;       // b_local = tb + 16*bi

    unsigned long long S2[4][4], A2[4][4];
    #pragma unroll
    for (int bi = 0; bi < 4; ++bi)
        #pragma unroll
        for (int vi = 0; vi < 4; ++vi) { S2[bi][vi] = 0ull; A2[bi][vi] = 0ull; }

    #pragma unroll 4
    for (int kq = 0; kq < 16; ++kq) {
        ulonglong2 P[4], Q[4];
        #pragma unroll
        for (int vi = 0; vi < 4; ++vi) {
            P[vi] = *(const ulonglong2*)&ph [tv + 16 * vi][kq * 4];
            Q[vi] = *(const ulonglong2*)&phL[tv + 16 * vi][kq * 4];
        }
        #pragma unroll
        for (int bi = 0; bi < 4; ++bi) {
            ulonglong2 T = *(const ulonglong2*)&th [tb + 16 * bi][kq * 4];
            ulonglong2 L = *(const ulonglong2*)&thL[tb + 16 * bi][kq * 4];
            #pragma unroll
            for (int vi = 0; vi < 4; ++vi) {
                pfma(S2[bi][vi], T.x, P[vi].x);
                pfma(S2[bi][vi], T.y, P[vi].y);
                pfma(A2[bi][vi], L.x, P[vi].x);
                pfma(A2[bi][vi], L.y, P[vi].y);
                pfma(A2[bi][vi], T.x, Q[vi].x);
                pfma(A2[bi][vi], T.y, Q[vi].y);
            }
        }
    }

    // epilogue of phase 1: w, entropy
    float wv[4][4];
    float ent = 0.f;
    #pragma unroll
    for (int bi = 0; bi < 4; ++bi) {
        int b = b0 + tb + 16 * bi;
        #pragma unroll
        for (int vi = 0; vi < 4; ++vi) {
            int v = v0 + tv + 16 * vi;
            int cnt = bow[b * Vc + v];
            float S = psum(S2[bi][vi]);
            float A = psum(A2[bi][vi]);
            float sp = S + MINIf;
            float r  = __fdividef(1.f, sp);
            wv[bi][vi] = (float)cnt * r;
            if (cnt > 0)
                ent += (A - S * __logf(sp)) * r;
        }
    }

    // block entropy reduction
    #pragma unroll
    for (int o = 16; o; o >>= 1)
        ent += __shfl_xor_sync(0xFFFFFFFFu, ent, o);
    __shared__ float ered[8];
    if ((t & 31) == 0) ered[t >> 5] = ent;

    __syncthreads();   // all thL reads done; ered visible
    if (t == 0) {
        float s = 0.f;
        #pragma unroll
        for (int w = 0; w < 8; ++w) s += ered[w];
        atomicAdd(&out[OUT_QZ], s);
    }

    // stage W into smem (overwrites thL)
    #pragma unroll
    for (int bi = 0; bi < 4; ++bi)
        #pragma unroll
        for (int vi = 0; vi < 4; ++vi)
            Wt[tb + 16 * bi][tv + 16 * vi] = wv[bi][vi];
    __syncthreads();

    // ---- phase 2 ----
    int kq2 = t & 15;            // k = kq2*4 .. +3
    int tr  = t >> 4;            // row group: tr + 16*j

    // 2a: Mpart[b_local, k] = sum_c Wt[b_local][c] * ph[c][k]
    {
        unsigned long long acc[4][2];
        #pragma unroll
        for (int j = 0; j < 4; ++j) { acc[j][0] = 0ull; acc[j][1] = 0ull; }
        #pragma unroll 8
        for (int c = 0; c < 64; ++c) {
            ulonglong2 p2 = *(const ulonglong2*)&ph[c][kq2 * 4];
            #pragma unroll
            for (int j = 0; j < 4; ++j) {
                float w = Wt[tr + 16 * j][c];
                unsigned long long w2 = fpack2(w, w);
                pfma(acc[j][0], w2, p2.x);
                pfma(acc[j][1], w2, p2.y);
            }
        }
        float* base = &g_Mpart[((blockIdx.x << 2) + blockIdx.y) * 4096];
        #pragma unroll
        for (int j = 0; j < 4; ++j) {
            float4 o4;
            punpack(acc[j][0], o4.x, o4.y);
            punpack(acc[j][1], o4.z, o4.w);
            *(float4*)&base[(tr + 16 * j) * 64 + kq2 * 4] = o4;
        }
    }

    // 2b: Nacc[v, k] += sum_c Wt[c][v_local] * th[c][k]   (atomics, depth 4)
    {
        unsigned long long acc[4][2];
        #pragma unroll
        for (int j = 0; j < 4; ++j) { acc[j][0] = 0ull; acc[j][1] = 0ull; }
        #pragma unroll 8
        for (int c = 0; c < 64; ++c) {
            ulonglong2 t2 = *(const ulonglong2*)&th[c][kq2 * 4];
            #pragma unroll
            for (int j = 0; j < 4; ++j) {
                float w = Wt[c][tr + 16 * j];
                unsigned long long w2 = fpack2(w, w);
                pfma(acc[j][0], w2, t2.x);
                pfma(acc[j][1], w2, t2.y);
            }
        }
        #pragma unroll
        for (int j = 0; j < 4; ++j) {
            float4 o4;
            punpack(acc[j][0], o4.x, o4.y);
            punpack(acc[j][1], o4.z, o4.w);
            float* dst = &g_Nacc[(v0 + tr + 16 * j) * Kc + kq2 * 4];
            atomicAdd(dst + 0, o4.x); atomicAdd(dst + 1, o4.y);
            atomicAdd(dst + 2, o4.z); atomicAdd(dst + 3, o4.w);
        }
    }
}

// ---------------------------------------------------------------------------
// K6: epilogue — Macc reduction from partials, apply factors, SVI updates.
__global__ void k6_epi(const float* __restrict__ expn,
                       const float* __restrict__ expm,
                       const unsigned int* __restrict__ idxw,
                       float* __restrict__ out) {
    int i = blockIdx.x * 256 + threadIdx.x;
    float rho = g_rho, omr = 1.f - rho;
    if (i < VK) {
        float tn = g_phi[i] * g_Nacc[i];
        out[OUT_TN + i] = tn;
        out[OUT_NN + i] = omr * expn[i] + rho * g_ratio * tn;
    } else if (i < VK + BK) {
        int j = i - VK;
        int b = j >> 6, k = j & 63;
        int bblk = b >> 6, bl = b & 63;
        float macc = 0.f;
        #pragma unroll 8
        for (int vblk = 0; vblk < 64; ++vblk)
            macc += g_Mpart[(vblk * 4 + bblk) * 4096 + bl * 64 + k];
        float tm = g_theta[j] * macc;
        out[OUT_TM + j] = tm;
        int d = (int)idxw[b * g_idxstride];
        out[OUT_NM + j] = omr * expm[d * Kc + k] + rho * tm;
    }
}

// ---------------------------------------------------------------------------
extern "C" void kernel_launch(void* const* d_in, const int* in_sizes, int n_in,
                              void* d_out, int out_size) {
    const int*          bow   = (const int*)d_in[0];
    const unsigned int* idxw  = (const unsigned int*)d_in[1];
    const float*        alpha = (const float*)d_in[2];
    const float*        pi    = (const float*)d_in[3];
    const float*        expm  = (const float*)d_in[4];
    const float*        beta  = (const float*)d_in[5];
    const float*        expn  = (const float*)d_in[6];
    const int*          iterp = (const int*)d_in[7];
    const int*          cmp   = (const int*)d_in[8];
    const int*          bcp   = (const int*)d_in[9];
    float* out = (float*)d_out;

    static int smem_set = 0;
    const int k3_smem = 256 * 68 * 4;  // 69632 bytes
    if (!smem_set) {
        cudaFuncSetAttribute(k3_fused, cudaFuncAttributeMaxDynamicSharedMemorySize, k3_smem);
        smem_set = 1;
    }

    k1_denom<<<Kc + 1, 256>>>(beta, expn, iterp, cmp, bcp, idxw, out);
    k2_prep<<<(2 * VK + BK) / 256, 256>>>(beta, expn, alpha, pi, expm, idxw);
    dim3 g3(Vc / 64, Bc / 64);
    k3_fused<<<g3, 256, k3_smem>>>(bow, out);
    k6_epi<<<(VK + BK) / 256, 256>>>(expn, expm, idxw, out);
}

// round 4
// speedup vs baseline: 1.7310x; 1.2057x over previous
#include <cuda_runtime.h>
#include <math.h>

#define Bc 256
#define Vc 4096
#define Kc 64
#define MINIf 1e-6f

#define VK (Vc*Kc)             /* 262144 */
#define BK (Bc*Kc)             /* 16384  */
#define OUT_TN 0
#define OUT_TM VK
#define OUT_QZ (VK+BK)
#define OUT_NN (VK+BK+1)
#define OUT_NM (VK+BK+1+VK)

// device scratch
__device__ float g_theta[BK];
__device__ float g_thetaL[BK];
__device__ float g_phi[VK];
__device__ float g_phiL[VK];
__device__ float g_Nacc[VK];
__device__ float g_Macc[BK];
__device__ float g_denom[Kc];
__device__ float g_rho;
__device__ float g_ratio;
__device__ int   g_idxstride;

// ---- packed f32x2 helpers (Blackwell FFMA2) --------------------------------
__device__ __forceinline__ void pfma(unsigned long long& acc,
                                     unsigned long long a, unsigned long long b) {
    asm("fma.rn.f32x2 %0, %1, %2, %0;" : "+l"(acc) : "l"(a), "l"(b));
}
__device__ __forceinline__ float psum(unsigned long long v) {
    return __uint_as_float((unsigned)v) + __uint_as_float((unsigned)(v >> 32));
}
__device__ __forceinline__ unsigned long long fpack2(float lo, float hi) {
    unsigned long long r;
    asm("mov.b64 %0, {%1, %2};" : "=l"(r) : "f"(lo), "f"(hi));
    return r;
}
__device__ __forceinline__ void punpack(unsigned long long v, float& lo, float& hi) {
    lo = __uint_as_float((unsigned)v);
    hi = __uint_as_float((unsigned)(v >> 32));
}

// ---------------------------------------------------------------------------
// K1: coalesced per-topic denominator (float4 + smem transpose + atomic),
//     plus scalars / index-dtype probe / entropy-slot zero in block 64.
__global__ void __launch_bounds__(256) k1_denom(
        const float* __restrict__ beta,
        const float* __restrict__ expn,
        const int* __restrict__ iterp,
        const int* __restrict__ cmp,
        const int* __restrict__ bcp,
        const unsigned int* __restrict__ idxw,
        float* __restrict__ out) {
    if (blockIdx.x < 64) {
        __shared__ float red[16][68];
        int t = threadIdx.x;
        int cq = t & 15, r = t >> 4;
        int v0 = blockIdx.x * 64;
        float4 a = make_float4(0.f, 0.f, 0.f, 0.f);
        #pragma unroll
        for (int j = 0; j < 4; ++j) {
            int row = v0 + r + 16 * j;
            float4 b4 = ((const float4*)beta)[row * 16 + cq];
            float4 e4 = ((const float4*)expn)[row * 16 + cq];
            a.x += b4.x + e4.x; a.y += b4.y + e4.y;
            a.z += b4.z + e4.z; a.w += b4.w + e4.w;
        }
        *(float4*)&red[r][cq * 4] = a;
        __syncthreads();
        if (t < 64) {
            float s = 0.f;
            #pragma unroll
            for (int r2 = 0; r2 < 16; ++r2) s += red[r2][t];
            atomicAdd(&g_denom[t], s);
        }
    } else if (threadIdx.x == 0) {
        g_rho   = 1.f / powf((float)(iterp[0] + 5), 0.9f);
        g_ratio = (float)cmp[0] / (float)bcp[0];
        // int64-vs-int32 probe: if int64, odd 32-bit words (high halves) are 0.
        bool allz = true;
        for (int i = 1; i < Bc; i += 2)
            if (idxw[i] != 0u) { allz = false; break; }
        g_idxstride = allz ? 2 : 1;
        out[OUT_QZ] = 0.f;
    }
}

// ---------------------------------------------------------------------------
// K2: phi, phi*log(phi), theta (gathered), theta*log(theta); zero accumulators.
__global__ void k2_prep(const float* __restrict__ beta,
                        const float* __restrict__ expn,
                        const float* __restrict__ alpha,
                        const float* __restrict__ pi,
                        const float* __restrict__ expm,
                        const unsigned int* __restrict__ idxw) {
    int i = blockIdx.x * 256 + threadIdx.x;
    if (i < VK) {
        int k = i & (Kc - 1);
        float p = __fdividef(beta[i] + expn[i], g_denom[k]);
        g_phi[i]  = p;
        g_phiL[i] = p * __logf(p);
        g_Nacc[i] = 0.f;
    } else if (i < VK + BK) {
        int j = i - VK;
        int b = j >> 6, k = j & 63;
        int d = (int)idxw[b * g_idxstride];
        float th = alpha[k] * pi[d * Kc + k] + expm[d * Kc + k];
        g_theta[j]  = th;
        g_thetaL[j] = th * __logf(th);
        g_Macc[j]   = 0.f;
    }
}

// ---------------------------------------------------------------------------
// K3 fused: per block 64b x 64v tile.
// Phase 1: S = theta.phi, A = thetaL.phi + theta.phiL ; w = cnt/(S+MINI);
//          entropy += (A - S*log(S+MINI))/(S+MINI) for cnt>0.
// Phase 2: Macc[b,:] += W(64x64) @ phi(64x64)    (float4 atomics)
//          Nacc[v,:] += W^T(64x64) @ theta(64x64) (float4 atomics)
__global__ void __launch_bounds__(256, 2)
k3_fused(const int* __restrict__ bow, float* __restrict__ out) {
    extern __shared__ float sm3[];
    float (*th)[68]  = (float(*)[68])(sm3);
    float (*thL)[68] = (float(*)[68])(sm3 + 64 * 68);   // becomes Wt in phase 2
    float (*ph)[68]  = (float(*)[68])(sm3 + 128 * 68);
    float (*phL)[68] = (float(*)[68])(sm3 + 192 * 68);
    float (*Wt)[68]  = thL;

    int t = threadIdx.x;
    int v0 = blockIdx.x * 64;
    int b0 = blockIdx.y * 64;

    for (int i = t; i < 64 * 16; i += 256) {
        int r = i >> 4, cq = i & 15;
        *(float4*)&th [r][cq * 4] = ((const float4*)g_theta )[(b0 + r) * 16 + cq];
        *(float4*)&thL[r][cq * 4] = ((const float4*)g_thetaL)[(b0 + r) * 16 + cq];
        *(float4*)&ph [r][cq * 4] = ((const float4*)g_phi   )[(v0 + r) * 16 + cq];
        *(float4*)&phL[r][cq * 4] = ((const float4*)g_phiL  )[(v0 + r) * 16 + cq];
    }
    __syncthreads();

    int tv = t & 15;       // v_local = tv + 16*vi
    int tb = t >> 4;       // b_local = tb + 16*bi

    unsigned long long S2[4][4], A2[4][4];
    #pragma unroll
    for (int bi = 0; bi < 4; ++bi)
        #pragma unroll
        for (int vi = 0; vi < 4; ++vi) { S2[bi][vi] = 0ull; A2[bi][vi] = 0ull; }

    #pragma unroll 4
    for (int kq = 0; kq < 16; ++kq) {
        ulonglong2 P[4], Q[4];
        #pragma unroll
        for (int vi = 0; vi < 4; ++vi) {
            P[vi] = *(const ulonglong2*)&ph [tv + 16 * vi][kq * 4];
            Q[vi] = *(const ulonglong2*)&phL[tv + 16 * vi][kq * 4];
        }
        #pragma unroll
        for (int bi = 0; bi < 4; ++bi) {
            ulonglong2 T = *(const ulonglong2*)&th [tb + 16 * bi][kq * 4];
            ulonglong2 L = *(const ulonglong2*)&thL[tb + 16 * bi][kq * 4];
            #pragma unroll
            for (int vi = 0; vi < 4; ++vi) {
                pfma(S2[bi][vi], T.x, P[vi].x);
                pfma(S2[bi][vi], T.y, P[vi].y);
                pfma(A2[bi][vi], L.x, P[vi].x);
                pfma(A2[bi][vi], L.y, P[vi].y);
                pfma(A2[bi][vi], T.x, Q[vi].x);
                pfma(A2[bi][vi], T.y, Q[vi].y);
            }
        }
    }

    // epilogue of phase 1: w, entropy
    float wv[4][4];
    float ent = 0.f;
    #pragma unroll
    for (int bi = 0; bi < 4; ++bi) {
        int b = b0 + tb + 16 * bi;
        #pragma unroll
        for (int vi = 0; vi < 4; ++vi) {
            int v = v0 + tv + 16 * vi;
            int cnt = bow[b * Vc + v];
            float S = psum(S2[bi][vi]);
            float A = psum(A2[bi][vi]);
            float sp = S + MINIf;
            float r  = __fdividef(1.f, sp);
            wv[bi][vi] = (float)cnt * r;
            if (cnt > 0)
                ent += (A - S * __logf(sp)) * r;
        }
    }

    // block entropy reduction
    #pragma unroll
    for (int o = 16; o; o >>= 1)
        ent += __shfl_xor_sync(0xFFFFFFFFu, ent, o);
    __shared__ float ered[8];
    if ((t & 31) == 0) ered[t >> 5] = ent;

    __syncthreads();   // all thL reads done; ered visible
    if (t == 0) {
        float s = 0.f;
        #pragma unroll
        for (int w = 0; w < 8; ++w) s += ered[w];
        atomicAdd(&out[OUT_QZ], s);
    }

    // stage W into smem (overwrites thL)
    #pragma unroll
    for (int bi = 0; bi < 4; ++bi)
        #pragma unroll
        for (int vi = 0; vi < 4; ++vi)
            Wt[tb + 16 * bi][tv + 16 * vi] = wv[bi][vi];
    __syncthreads();

    // ---- phase 2 ----
    int kq2 = t & 15;            // k = kq2*4 .. +3
    int tr  = t >> 4;            // row group: tr + 16*j

    // 2a: Macc[b, k] += sum_c Wt[b_local][c] * ph[c][k]   (float4 atomics)
    {
        unsigned long long acc[4][2];
        #pragma unroll
        for (int j = 0; j < 4; ++j) { acc[j][0] = 0ull; acc[j][1] = 0ull; }
        #pragma unroll 8
        for (int c = 0; c < 64; ++c) {
            ulonglong2 p2 = *(const ulonglong2*)&ph[c][kq2 * 4];
            #pragma unroll
            for (int j = 0; j < 4; ++j) {
                float w = Wt[tr + 16 * j][c];
                unsigned long long w2 = fpack2(w, w);
                pfma(acc[j][0], w2, p2.x);
                pfma(acc[j][1], w2, p2.y);
            }
        }
        #pragma unroll
        for (int j = 0; j < 4; ++j) {
            float4 o4;
            punpack(acc[j][0], o4.x, o4.y);
            punpack(acc[j][1], o4.z, o4.w);
            atomicAdd((float4*)&g_Macc[(b0 + tr + 16 * j) * Kc + kq2 * 4], o4);
        }
    }

    // 2b: Nacc[v, k] += sum_c Wt[c][v_local] * th[c][k]   (float4 atomics)
    {
        unsigned long long acc[4][2];
        #pragma unroll
        for (int j = 0; j < 4; ++j) { acc[j][0] = 0ull; acc[j][1] = 0ull; }
        #pragma unroll 8
        for (int c = 0; c < 64; ++c) {
            ulonglong2 t2 = *(const ulonglong2*)&th[c][kq2 * 4];
            #pragma unroll
            for (int j = 0; j < 4; ++j) {
                float w = Wt[c][tr + 16 * j];
                unsigned long long w2 = fpack2(w, w);
                pfma(acc[j][0], w2, t2.x);
                pfma(acc[j][1], w2, t2.y);
            }
        }
        #pragma unroll
        for (int j = 0; j < 4; ++j) {
            float4 o4;
            punpack(acc[j][0], o4.x, o4.y);
            punpack(acc[j][1], o4.z, o4.w);
            atomicAdd((float4*)&g_Nacc[(v0 + tr + 16 * j) * Kc + kq2 * 4], o4);
        }
    }
}

// ---------------------------------------------------------------------------
// K6: epilogue — pure streaming, float4 loads, scalar stores only where
// the output offset is unaligned (OUT_NN/OUT_NM are odd offsets).
__global__ void __launch_bounds__(256) k6_epi(
        const float* __restrict__ expn,
        const float* __restrict__ expm,
        const unsigned int* __restrict__ idxw,
        float* __restrict__ out) {
    float rho = g_rho, omr = 1.f - rho, rr = rho * g_ratio;
    if (blockIdx.x < 256) {
        int i4 = blockIdx.x * 256 + threadIdx.x;       // 0..65535 (VK/4)
        float4 p = ((const float4*)g_phi )[i4];
        float4 n = ((const float4*)g_Nacc)[i4];
        float4 e = ((const float4*)expn  )[i4];
        float4 tn = make_float4(p.x * n.x, p.y * n.y, p.z * n.z, p.w * n.w);
        ((float4*)(out + OUT_TN))[i4] = tn;
        int base = OUT_NN + i4 * 4;
        out[base + 0] = omr * e.x + rr * tn.x;
        out[base + 1] = omr * e.y + rr * tn.y;
        out[base + 2] = omr * e.z + rr * tn.z;
        out[base + 3] = omr * e.w + rr * tn.w;
    } else {
        int i4 = (blockIdx.x - 256) * 256 + threadIdx.x;   // 0..4095 (BK/4)
        int j = i4 * 4;
        int b = j >> 6, k = j & 63;
        float4 t4 = ((const float4*)g_theta)[i4];
        float4 m4 = ((const float4*)g_Macc)[i4];
        float4 tm = make_float4(t4.x * m4.x, t4.y * m4.y, t4.z * m4.z, t4.w * m4.w);
        ((float4*)(out + OUT_TM))[i4] = tm;
        int d = (int)idxw[b * g_idxstride];
        float4 em = ((const float4*)expm)[d * 16 + (k >> 2)];
        int base = OUT_NM + j;
        out[base + 0] = omr * em.x + rho * tm.x;
        out[base + 1] = omr * em.y + rho * tm.y;
        out[base + 2] = omr * em.z + rho * tm.z;
        out[base + 3] = omr * em.w + rho * tm.w;
    }
}

// ---------------------------------------------------------------------------
extern "C" void kernel_launch(void* const* d_in, const int* in_sizes, int n_in,
                              void* d_out, int out_size) {
    const int*          bow   = (const int*)d_in[0];
    const unsigned int* idxw  = (const unsigned int*)d_in[1];
    const float*        alpha = (const float*)d_in[2];
    const float*        pi    = (const float*)d_in[3];
    const float*        expm  = (const float*)d_in[4];
    const float*        beta  = (const float*)d_in[5];
    const float*        expn  = (const float*)d_in[6];
    const int*          iterp = (const int*)d_in[7];
    const int*          cmp   = (const int*)d_in[8];
    const int*          bcp   = (const int*)d_in[9];
    float* out = (float*)d_out;

    static int smem_set = 0;
    const int k3_smem = 256 * 68 * 4;  // 69632 bytes
    if (!smem_set) {
        cudaFuncSetAttribute(k3_fused, cudaFuncAttributeMaxDynamicSharedMemorySize, k3_smem);
        smem_set = 1;
    }

    void* denom_ptr = nullptr;
    cudaGetSymbolAddress(&denom_ptr, g_denom);
    cudaMemsetAsync(denom_ptr, 0, Kc * sizeof(float));

    k1_denom<<<65, 256>>>(beta, expn, iterp, cmp, bcp, idxw, out);
    k2_prep<<<(VK + BK) / 256, 256>>>(beta, expn, alpha, pi, expm, idxw);
    dim3 g3(Vc / 64, Bc / 64);
    k3_fused<<<g3, 256, k3_smem>>>(bow, out);
    k6_epi<<<256 + 16, 256>>>(expn, expm, idxw, out);
}